// round 15
// baseline (speedup 1.0000x reference)
#include <cuda_runtime.h>
#include <cstddef>
#include <cstdint>

#define BB 4
#define NN 8192
#define CC 64
#define SS 2048
#define KK 32
#define R2 0.04f

#define GROUPED_OFF (BB * SS * 3)                       /* 24576 */
#define FPS_OFF (GROUPED_OFF + BB * (CC + 3) * SS * KK) /* 24576 + 17563648 */

#define PPW (NN / 8)        /* 1024 points per warp in the fused query */

// scratch (static device globals: no allocation in kernel_launch)
__device__ float g_ft[(size_t)BB * NN * CC]; // 8 MB, features transposed to (B,N,C)
__device__ float g_sx[BB * NN];              // SoA coords for the query scan
__device__ float g_sy[BB * NN];
__device__ float g_sz[BB * NN];
__device__ int   g_order[BB * NN];           // morton-sorted original indices
__device__ float g_sxyz[BB * NN * 3];        // coords gathered in sorted order

// ---------------------------------------------------------------------------
// packed f32x2 helpers (Blackwell FFMA2 path — only reachable via PTX f32x2)
// ---------------------------------------------------------------------------
typedef unsigned long long u64;

__device__ __forceinline__ u64 pk2(float lo, float hi) {
    u64 r; asm("mov.b64 %0, {%1, %2};" : "=l"(r) : "f"(lo), "f"(hi)); return r;
}
__device__ __forceinline__ void upk2(u64 v, float& lo, float& hi) {
    asm("mov.b64 {%0, %1}, %2;" : "=f"(lo), "=f"(hi) : "l"(v));
}
__device__ __forceinline__ u64 add2(u64 a, u64 b) {
    u64 r; asm("add.rn.f32x2 %0, %1, %2;" : "=l"(r) : "l"(a), "l"(b)); return r;
}
__device__ __forceinline__ u64 mul2(u64 a, u64 b) {
    u64 r; asm("mul.rn.f32x2 %0, %1, %2;" : "=l"(r) : "l"(a), "l"(b)); return r;
}
__device__ __forceinline__ u64 fma2(u64 a, u64 b, u64 c) {
    u64 r; asm("fma.rn.f32x2 %0, %1, %2, %3;" : "=l"(r) : "l"(a), "l"(b), "l"(c)); return r;
}

// ---------------------------------------------------------------------------
// xyz (B,N,3) -> SoA g_sx/g_sy/g_sz (coalesced loads for the query scan)
// ---------------------------------------------------------------------------
__global__ void soa_kernel(const float* __restrict__ xyz) {
    const int b = blockIdx.y;
    const int i = blockIdx.x * 256 + threadIdx.x;
    const float* p = xyz + ((size_t)b * NN + i) * 3;
    g_sx[b * NN + i] = p[0];
    g_sy[b * NN + i] = p[1];
    g_sz[b * NN + i] = p[2];
}

// ---------------------------------------------------------------------------
// features (B,C,N) -> (B,N,C)
// ---------------------------------------------------------------------------
__global__ void transpose_kernel(const float* __restrict__ f) {
    __shared__ float tile[32][33];
    const int b  = blockIdx.z;
    const int n0 = blockIdx.x * 32;
    const int c0 = blockIdx.y * 32;
    const float* fb = f + (size_t)b * CC * NN;
#pragma unroll
    for (int j = 0; j < 32; j += 8)
        tile[threadIdx.y + j][threadIdx.x] =
            fb[(size_t)(c0 + threadIdx.y + j) * NN + (n0 + threadIdx.x)];
    __syncthreads();
    float* fo = g_ft + (size_t)b * NN * CC;
#pragma unroll
    for (int j = 0; j < 32; j += 8)
        fo[(size_t)(n0 + threadIdx.y + j) * CC + (c0 + threadIdx.x)] =
            tile[threadIdx.x][threadIdx.y + j];
}

// ---------------------------------------------------------------------------
// morton sort (R8, verified): one CTA per batch; bitonic sort of
// (morton18|idx13) u32 keys. Only SPEED depends on this (any permutation is
// correct for FPS).
// ---------------------------------------------------------------------------
__device__ __forceinline__ unsigned spread3(unsigned x) {
    x &= 0x3FFu;
    x = (x | (x << 16)) & 0x30000FFu;
    x = (x | (x << 8))  & 0x300F00Fu;
    x = (x | (x << 4))  & 0x30C30C3u;
    x = (x | (x << 2))  & 0x9249249u;
    return x;
}
__device__ __forceinline__ unsigned quant6(float v) {
    int q = (int)((v + 4.5f) * (64.0f / 9.0f));
    return (unsigned)max(0, min(63, q));
}

__global__ void __launch_bounds__(1024, 1)
sort_kernel(const float* __restrict__ xyz) {
    __shared__ unsigned keys[NN];               // 32 KB
    const int b = blockIdx.x;
    const float* base = xyz + (size_t)b * NN * 3;
    const int t = threadIdx.x;

    for (int i = t; i < NN; i += 1024) {
        const unsigned mx = spread3(quant6(base[3 * i + 0]));
        const unsigned my = spread3(quant6(base[3 * i + 1]));
        const unsigned mz = spread3(quant6(base[3 * i + 2]));
        const unsigned m = mx | (my << 1) | (mz << 2);   // 18 bits
        keys[i] = (m << 13) | (unsigned)i;               // unique keys
    }
    __syncthreads();

    for (unsigned k = 2; k <= NN; k <<= 1) {
        for (unsigned j = k >> 1; j > 0; j >>= 1) {
#pragma unroll 1
            for (unsigned m = t; m < NN / 2; m += 1024) {
                const unsigned i = ((m & ~(j - 1)) << 1) | (m & (j - 1));
                const unsigned p = i | j;
                const bool up = ((i & k) == 0);
                const unsigned a = keys[i], c = keys[p];
                if ((a > c) == up) { keys[i] = c; keys[p] = a; }
            }
            __syncthreads();
        }
    }

    for (int i = t; i < NN; i += 1024) {
        const unsigned oi = keys[i] & (NN - 1);
        g_order[b * NN + i] = (int)oi;
        g_sxyz[((size_t)b * NN + i) * 3 + 0] = base[3 * oi + 0];
        g_sxyz[((size_t)b * NN + i) * 3 + 1] = base[3 * oi + 1];
        g_sxyz[((size_t)b * NN + i) * 3 + 2] = base[3 * oi + 2];
    }
}

// ---------------------------------------------------------------------------
// FPS with WARP-UNIFORM sub-block culling. 256 threads/batch, 32 pts/thread.
// Warp w owns sorted positions [w*1024,(w+1)*1024), as 4 contiguous 256-pt
// sub-blocks; one bounding sphere per sub-block (uniform across the warp).
// Per iteration, per sub-block: ONE uniform test; on skip the whole warp
// bypasses that block's md update (provably exact via R8 margin recipe).
// Tail (atomicMax / bar / lazy holder scan / atomicMin / bar) = champion.
// writes new_xyz (out[0..]) and fps_idx (out[FPS_OFF..], as float)
// ---------------------------------------------------------------------------
__global__ void __launch_bounds__(256, 1)
fps_kernel(const float* __restrict__ xyz, float* __restrict__ out) {
    const int b = blockIdx.x;
    const float* base = xyz + (size_t)b * NN * 3;     // original order (centers)
    const float* sxp  = g_sxyz + (size_t)b * NN * 3;  // sorted AoS
    float* newxyz = out + (size_t)b * SS * 3;
    float* fpsout = out + FPS_OFF + (size_t)b * SS;
    const int t = threadIdx.x;
    const int lane = t & 31;
    const int w = t >> 5;

    __shared__ int s_ord[NN];           // 32 KB: sorted pos -> original index
    for (int i = t; i < NN; i += 256)
        s_ord[i] = g_order[b * NN + i];

    // block k of warp w: sorted positions [w*1024 + k*256, +256)
    // lane L, slot m (0..7): pos = w*1024 + k*256 + m*32 + L
    // register pair j packs slots (2j, 2j+1); md index = k*8 + m
    u64 npx[16], npy[16], npz[16];      // [k*4 + j], stored NEGATED
    float md[32];
    float gcx[4], gcy[4], gcz[4], rr[4], Tt[4], gval[4], lm[4];

#pragma unroll
    for (int k = 0; k < 4; k++) {
        float mnx = 1e30f, mxx = -1e30f, mny = 1e30f, mxy = -1e30f;
        float mnz = 1e30f, mxz = -1e30f;
#pragma unroll
        for (int j = 0; j < 4; j++) {
            const int p0 = w * 1024 + k * 256 + (2 * j) * 32 + lane;
            const int p1 = p0 + 32;
            const float x0 = sxp[p0 * 3 + 0], y0 = sxp[p0 * 3 + 1], z0 = sxp[p0 * 3 + 2];
            const float x1 = sxp[p1 * 3 + 0], y1 = sxp[p1 * 3 + 1], z1 = sxp[p1 * 3 + 2];
            npx[k * 4 + j] = pk2(-x0, -x1);
            npy[k * 4 + j] = pk2(-y0, -y1);
            npz[k * 4 + j] = pk2(-z0, -z1);
            mnx = fminf(mnx, fminf(x0, x1)); mxx = fmaxf(mxx, fmaxf(x0, x1));
            mny = fminf(mny, fminf(y0, y1)); mxy = fmaxf(mxy, fmaxf(y0, y1));
            mnz = fminf(mnz, fminf(z0, z1)); mxz = fmaxf(mxz, fmaxf(z0, z1));
            md[k * 8 + 2 * j] = 1e10f; md[k * 8 + 2 * j + 1] = 1e10f;
        }
        // warp-wide min/max -> uniform sphere
#pragma unroll
        for (int off = 16; off > 0; off >>= 1) {
            mnx = fminf(mnx, __shfl_xor_sync(0xffffffffu, mnx, off));
            mxx = fmaxf(mxx, __shfl_xor_sync(0xffffffffu, mxx, off));
            mny = fminf(mny, __shfl_xor_sync(0xffffffffu, mny, off));
            mxy = fmaxf(mxy, __shfl_xor_sync(0xffffffffu, mxy, off));
            mnz = fminf(mnz, __shfl_xor_sync(0xffffffffu, mnz, off));
            mxz = fmaxf(mxz, __shfl_xor_sync(0xffffffffu, mxz, off));
        }
        gcx[k] = 0.5f * (mnx + mxx);
        gcy[k] = 0.5f * (mny + mxy);
        gcz[k] = 0.5f * (mnz + mxz);
        float r2m = 0.0f;
#pragma unroll
        for (int j = 0; j < 4; j++) {
            float x0, x1, y0, y1, z0, z1;
            upk2(npx[k * 4 + j], x0, x1);
            upk2(npy[k * 4 + j], y0, y1);
            upk2(npz[k * 4 + j], z0, z1);
            const float dx0 = gcx[k] + x0, dy0 = gcy[k] + y0, dz0 = gcz[k] + z0;
            const float dx1 = gcx[k] + x1, dy1 = gcy[k] + y1, dz1 = gcz[k] + z1;
            r2m = fmaxf(r2m, __fmaf_rn(dz0, dz0, __fmaf_rn(dy0, dy0, dx0 * dx0)));
            r2m = fmaxf(r2m, __fmaf_rn(dz1, dz1, __fmaf_rn(dy1, dy1, dx1 * dx1)));
        }
#pragma unroll
        for (int off = 16; off > 0; off >>= 1)
            r2m = fmaxf(r2m, __shfl_xor_sync(0xffffffffu, r2m, off));
        rr[k]   = sqrtf(r2m) * 1.00002f + 1e-7f;   // inflated block radius
        gval[k] = 1e10f;
        lm[k]   = 1e10f;
        const float rt = rr[k] + sqrtf(1e10f) * 1.00001f;
        Tt[k] = rt * rt;
    }

    __shared__ unsigned s_bmax[2];      // [buf] block max (float bits, >=0)
    __shared__ int      s_gi[2];        // [buf] winning ORIGINAL index
    if (t < 2) { s_bmax[t] = 0u; s_gi[t] = 0x7fffffff; }

    float cx = base[0], cy = base[1], cz = base[2];
    if (t == 0) {
        fpsout[0] = 0.0f;
        newxyz[0] = cx; newxyz[1] = cy; newxyz[2] = cz;
    }
    __syncthreads();    // order smem init (s_ord + flags) before the loop

    for (int i = 1; i < SS; i++) {
        const int buf = i & 1;
        const u64 cx2 = pk2(cx, cx);
        const u64 cy2 = pk2(cy, cy);
        const u64 cz2 = pk2(cz, cz);

#pragma unroll
        for (int k = 0; k < 4; k++) {
            // warp-uniform sphere test (all inputs uniform across the warp)
            const float dxc = cx - gcx[k], dyc = cy - gcy[k], dzc = cz - gcz[k];
            const float dc2 = __fmaf_rn(dzc, dzc, __fmaf_rn(dyc, dyc, dxc * dxc));
            if (dc2 * 0.99996f < Tt[k]) {
                // block may change: md update (bit-identical to reference)
                float m2[4];
#pragma unroll
                for (int j = 0; j < 4; j++) {
                    const u64 dx = add2(cx2, npx[k * 4 + j]);   // cx - px
                    const u64 dy = add2(cy2, npy[k * 4 + j]);
                    const u64 dz = add2(cz2, npz[k * 4 + j]);
                    const u64 d  = fma2(dz, dz, fma2(dy, dy, mul2(dx, dx)));
                    float dl, dh; upk2(d, dl, dh);
                    md[k * 8 + 2 * j]     = fminf(md[k * 8 + 2 * j], dl);
                    md[k * 8 + 2 * j + 1] = fminf(md[k * 8 + 2 * j + 1], dh);
                    m2[j] = fmaxf(md[k * 8 + 2 * j], md[k * 8 + 2 * j + 1]);
                }
                lm[k] = fmaxf(fmaxf(m2[0], m2[1]), fmaxf(m2[2], m2[3]));
                // block max (md >= 0: float bits order-isomorphic to u32)
                const unsigned gmu =
                    __reduce_max_sync(0xffffffffu, __float_as_uint(lm[k]));
                gval[k] = __uint_as_float(gmu);
                const float rt = rr[k] + sqrtf(gval[k]) * 1.00001f;
                Tt[k] = rt * rt;
            }
        }

        // value phase: warp value is a max of 4 uniform scalars (no REDUX)
        const float wv = fmaxf(fmaxf(gval[0], gval[1]), fmaxf(gval[2], gval[3]));
        if (lane == 0) atomicMax(&s_bmax[buf], __float_as_uint(wv));
        __syncthreads();                                   // bar1

        const unsigned bmax = s_bmax[buf];
        if (t == 0) {                 // reset-ahead for next iteration's buffer
            s_bmax[buf ^ 1] = 0u;
            s_gi[buf ^ 1]   = 0x7fffffff;
        }

        // lazy index resolution: only lanes holding the block max scan;
        // original indices from SMEM; lowest original index wins (jnp.argmax).
        const float mymax = fmaxf(fmaxf(lm[0], lm[1]), fmaxf(lm[2], lm[3]));
        if (__float_as_uint(mymax) == bmax) {
            const float bvv = mymax;
            int best = 0x7fffffff;
#pragma unroll
            for (int k = 0; k < 4; k++)
#pragma unroll
                for (int m = 0; m < 8; m++)
                    if (md[k * 8 + m] == bvv)
                        best = min(best, s_ord[w * 1024 + k * 256 + m * 32 + lane]);
            atomicMin(&s_gi[buf], best);
        }
        __syncthreads();                                   // bar2

        const int gi = s_gi[buf];
        cx = base[(size_t)gi * 3 + 0];   // same addr per warp -> L1 broadcast
        cy = base[(size_t)gi * 3 + 1];
        cz = base[(size_t)gi * 3 + 2];
        if (t == 0) {
            fpsout[i] = (float)gi;
            newxyz[(size_t)i * 3 + 0] = cx;
            newxyz[(size_t)i * 3 + 1] = cy;
            newxyz[(size_t)i * 3 + 2] = cz;
        }
    }
}

// ---------------------------------------------------------------------------
// fused ball query + grouping (R10/R14, verified, 67us): one block per center.
// 8 warps partition the N points into index-contiguous 1024-pt ranges; each
// ballot-scans its range with packed f32x2 math (2 pts/lane/round, order kept:
// lo = [p0,p0+32), hi = [p0+32,p0+64)). Ranges are index-ordered, so first-K
// overall = concat of per-warp ordered lists, merged in smem. Pad = first
// overall hit (0 if none). Then grouping: coalesced feature-row staging and
// K-contiguous channel-major writes.
// out grouped layout: (B, 3+C, S, K), channels 0..2 = recentered xyz
// ---------------------------------------------------------------------------
__global__ void __launch_bounds__(256, 4)
group_kernel(const float* __restrict__ xyz, float* __restrict__ out) {
    const int cid = blockIdx.x;
    const int b = cid / SS, s = cid % SS;
    const int tid = threadIdx.x;
    const int w = tid >> 5, lane = tid & 31;

    __shared__ int   hits[8][KK];
    __shared__ int   scnt[8];
    __shared__ int   sidx[KK];
    __shared__ float rel[3][KK];
    __shared__ float sf[KK][CC + 1];

    const float* c = out + (size_t)cid * 3;      // new_xyz lives at start of out
    const float cx = c[0], cy = c[1], cz = c[2];
    const u64 ncx = pk2(-cx, -cx), ncy = pk2(-cy, -cy), ncz = pk2(-cz, -cz);

    const float* sxp = g_sx + b * NN;
    const float* syp = g_sy + b * NN;
    const float* szp = g_sz + b * NN;

    // per-warp ordered scan of its 1024-point range
    int cnt = 0;
    const int pbeg = w * PPW;
    for (int p0 = pbeg; p0 < pbeg + PPW && cnt < KK; p0 += 64) {
        const int lo = p0 + lane, hi = p0 + 32 + lane;
        const u64 px = pk2(sxp[lo], sxp[hi]);
        const u64 py = pk2(syp[lo], syp[hi]);
        const u64 pz = pk2(szp[lo], szp[hi]);
        const u64 dx = add2(px, ncx);
        const u64 dy = add2(py, ncy);
        const u64 dz = add2(pz, ncz);
        const u64 d  = fma2(dz, dz, fma2(dy, dy, mul2(dx, dx)));
        float dl, dh; upk2(d, dl, dh);
        const bool hl = dl < R2, hh = dh < R2;
        const unsigned mlo = __ballot_sync(0xffffffffu, hl);
        const unsigned mhi = __ballot_sync(0xffffffffu, hh);
        if (mlo | mhi) {
            if (cnt == 0) {
                const int first = mlo ? (p0 + __ffs(mlo) - 1)
                                      : (p0 + 32 + __ffs(mhi) - 1);
                hits[w][lane] = first;          // pad all K slots with first hit
            }
            __syncwarp();
            const unsigned below = (1u << lane) - 1u;
            if (hl) {
                const int slot = cnt + __popc(mlo & below);
                if (slot < KK) hits[w][slot] = lo;
            }
            if (hh) {
                const int slot = cnt + __popc(mlo) + __popc(mhi & below);
                if (slot < KK) hits[w][slot] = hi;
            }
            cnt += __popc(mlo) + __popc(mhi);
        }
    }
    if (lane == 0) scnt[w] = min(cnt, KK);
    __syncthreads();

    // merge: warp 0, lane k picks the k-th hit of the 8 concatenated lists
    if (w == 0) {
        int idx = -1, acc = 0;
#pragma unroll
        for (int v = 0; v < 8; v++) {
            const int cv = scnt[v];
            if (lane >= acc && lane < acc + cv) idx = hits[v][lane - acc];
            acc += cv;
        }
        int pad = 0;
#pragma unroll
        for (int v = 7; v >= 0; v--)
            if (scnt[v] > 0) pad = hits[v][0];
        if (lane >= acc) idx = pad;             // acc = total hits (capped)
        sidx[lane] = idx;
        const float* p = xyz + ((size_t)b * NN + idx) * 3;
        rel[0][lane] = p[0] - cx;
        rel[1][lane] = p[1] - cy;
        rel[2][lane] = p[2] - cz;
    }
    __syncthreads();

    // feature staging: coalesced 256B row reads
    const int cch = tid & 63;
    const int k0  = tid >> 6;   // 0..3
    const float* ftb = g_ft + (size_t)b * NN * CC;
#pragma unroll
    for (int j = 0; j < 8; j++) {
        const int k = k0 * 8 + j;
        sf[k][cch] = ftb[(size_t)sidx[k] * CC + cch];
    }
    __syncthreads();

    float* og = out + GROUPED_OFF + (size_t)b * (CC + 3) * SS * KK + (size_t)s * KK;
    if (tid < 96) {
        const int ch = tid >> 5, k = tid & 31;
        og[(size_t)ch * (SS * KK) + k] = rel[ch][k];
    }
    const int k  = tid & 31;
    const int cg = tid >> 5;    // 0..7
#pragma unroll
    for (int j = 0; j < 8; j++) {
        const int c2 = cg * 8 + j;
        og[(size_t)(3 + c2) * (SS * KK) + k] = sf[k][c2];
    }
}

// ---------------------------------------------------------------------------
extern "C" void kernel_launch(void* const* d_in, const int* in_sizes, int n_in,
                              void* d_out, int out_size) {
    const float* xyz  = (const float*)d_in[0];
    const float* feat = (const float*)d_in[1];
    float* out = (float*)d_out;

    sort_kernel<<<BB, 1024>>>(xyz);
    soa_kernel<<<dim3(NN / 256, BB), 256>>>(xyz);
    transpose_kernel<<<dim3(NN / 32, CC / 32, BB), dim3(32, 8)>>>(feat);
    fps_kernel<<<BB, 256>>>(xyz, out);
    group_kernel<<<BB * SS, 256>>>(xyz, out);
}

// round 16
// speedup vs baseline: 1.6721x; 1.6721x over previous
#include <cuda_runtime.h>
#include <cstddef>
#include <cstdint>

#define BB 4
#define NN 8192
#define CC 64
#define SS 2048
#define KK 32
#define R2 0.04f

#define GROUPED_OFF (BB * SS * 3)                       /* 24576 */
#define FPS_OFF (GROUPED_OFF + BB * (CC + 3) * SS * KK) /* 24576 + 17563648 */

#define NWORK 144            /* prep CTAs (exit after prep; no spinning) */
#define GRID (BB + NWORK)    /* 148 CTAs, one wave */
#define PPW (NN / 8)         /* 1024 points per warp in the fused query */

// scratch (static device globals: no allocation in kernel_launch)
__device__ float g_ft[(size_t)BB * NN * CC]; // 8 MB, features (B,N,C)
__device__ float g_sx[BB * NN];              // SoA coords for the query scan
__device__ float g_sy[BB * NN];
__device__ float g_sz[BB * NN];

// ---------------------------------------------------------------------------
// packed f32x2 helpers (Blackwell FFMA2 path — only reachable via PTX f32x2)
// ---------------------------------------------------------------------------
typedef unsigned long long u64;

__device__ __forceinline__ u64 pk2(float lo, float hi) {
    u64 r; asm("mov.b64 %0, {%1, %2};" : "=l"(r) : "f"(lo), "f"(hi)); return r;
}
__device__ __forceinline__ void upk2(u64 v, float& lo, float& hi) {
    asm("mov.b64 {%0, %1}, %2;" : "=f"(lo), "=f"(hi) : "l"(v));
}
__device__ __forceinline__ u64 add2(u64 a, u64 b) {
    u64 r; asm("add.rn.f32x2 %0, %1, %2;" : "=l"(r) : "l"(a), "l"(b)); return r;
}
__device__ __forceinline__ u64 mul2(u64 a, u64 b) {
    u64 r; asm("mul.rn.f32x2 %0, %1, %2;" : "=l"(r) : "l"(a), "l"(b)); return r;
}
__device__ __forceinline__ u64 fma2(u64 a, u64 b, u64 c) {
    u64 r; asm("fma.rn.f32x2 %0, %1, %2, %3;" : "=l"(r) : "l"(a), "l"(b), "l"(c)); return r;
}

// ---------------------------------------------------------------------------
// ONE launch for prep + FPS:
//   blocks 0..3    : champion FPS for batch b (byte-identical decision path).
//   blocks 4..147  : prep (xyz->SoA, features (B,C,N)->(B,N,C)), then EXIT.
// No cross-CTA sync: prep outputs are read only by group_kernel, which starts
// after this kernel completes. Prep CTAs finish in ~5us, leaving the chip idle
// (= high NAT clocks) for the serial FPS tail.
// ---------------------------------------------------------------------------
__global__ void __launch_bounds__(256, 1)
prep_fps_kernel(const float* __restrict__ xyz, const float* __restrict__ feat,
                float* __restrict__ out) {
    const int tid = threadIdx.x;

    if (blockIdx.x >= BB) {
        // ================= prep worker (exit after) =================
        const int wid = blockIdx.x - BB;

        // xyz -> SoA
        for (int idx = wid * 256 + tid; idx < BB * NN; idx += NWORK * 256) {
            const float* p = xyz + (size_t)idx * 3;
            g_sx[idx] = p[0];
            g_sy[idx] = p[1];
            g_sz[idx] = p[2];
        }

        // features (B,C,N) -> (B,N,C), 32x32 tiles
        __shared__ float tile[32][33];
        const int lx = tid & 31, ly = tid >> 5;          // 32 x 8
        for (int tt = wid; tt < (NN / 32) * (CC / 32) * BB; tt += NWORK) {
            const int b  = tt >> 9;                      // / 512
            const int rm = tt & 511;
            const int c0 = (rm >> 8) << 5;               // 0 or 32
            const int n0 = (rm & 255) << 5;
            const float* fb = feat + (size_t)b * CC * NN;
            __syncthreads();                             // tile reuse guard
#pragma unroll
            for (int j = 0; j < 32; j += 8)
                tile[ly + j][lx] = fb[(size_t)(c0 + ly + j) * NN + (n0 + lx)];
            __syncthreads();
            float* fo = g_ft + (size_t)b * NN * CC;
#pragma unroll
            for (int j = 0; j < 32; j += 8)
                fo[(size_t)(n0 + ly + j) * CC + (c0 + lx)] = tile[lx][ly + j];
        }
        return;
    }

    // ================= FPS (1056us champion, byte-identical) =================
    const int b = blockIdx.x;
    const float* base = xyz + (size_t)b * NN * 3;
    float* newxyz = out + (size_t)b * SS * 3;
    float* fpsout = out + FPS_OFF + (size_t)b * SS;
    const int t = tid;
    const int lane = t & 31;

    // pair j holds points (t + 2j*256, t + (2j+1)*256), stored NEGATED
    u64 npx[16], npy[16], npz[16];
    float md[32];
#pragma unroll
    for (int j = 0; j < 16; j++) {
        const int p0 = t + (2 * j) * 256;
        const int p1 = p0 + 256;
        npx[j] = pk2(-base[p0 * 3 + 0], -base[p1 * 3 + 0]);
        npy[j] = pk2(-base[p0 * 3 + 1], -base[p1 * 3 + 1]);
        npz[j] = pk2(-base[p0 * 3 + 2], -base[p1 * 3 + 2]);
        md[2 * j] = 1e10f; md[2 * j + 1] = 1e10f;
    }

    __shared__ unsigned s_bmax[2];      // [buf] block max (float bits, >=0)
    __shared__ int      s_gi[2];        // [buf] winning global index
    if (t < 2) { s_bmax[t] = 0u; s_gi[t] = 0x7fffffff; }

    float cx = base[0], cy = base[1], cz = base[2];
    if (t == 0) {
        fpsout[0] = 0.0f;
        newxyz[0] = cx; newxyz[1] = cy; newxyz[2] = cz;
    }
    __syncthreads();    // order smem init before iter-1 atomicMax

    for (int i = 1; i < SS; i++) {
        const int buf = i & 1;
        const u64 cx2 = pk2(cx, cx);
        const u64 cy2 = pk2(cy, cy);
        const u64 cz2 = pk2(cz, cz);

        float m2[16];
#pragma unroll
        for (int j = 0; j < 16; j++) {
            const u64 dx = add2(cx2, npx[j]);          // cx - px
            const u64 dy = add2(cy2, npy[j]);
            const u64 dz = add2(cz2, npz[j]);
            const u64 d  = fma2(dz, dz, fma2(dy, dy, mul2(dx, dx)));
            float dl, dh; upk2(d, dl, dh);
            md[2 * j]     = fminf(md[2 * j], dl);
            md[2 * j + 1] = fminf(md[2 * j + 1], dh);
            m2[j] = fmaxf(md[2 * j], md[2 * j + 1]);
        }
        float m4[8];
#pragma unroll
        for (int j = 0; j < 8; j++) m4[j] = fmaxf(m2[2 * j], m2[2 * j + 1]);
        float m8[4];
#pragma unroll
        for (int j = 0; j < 4; j++) m8[j] = fmaxf(m4[2 * j], m4[2 * j + 1]);
        const float bv = fmaxf(fmaxf(m8[0], m8[1]), fmaxf(m8[2], m8[3]));

        // value phase (md >= 0: float bits order-isomorphic to u32)
        const unsigned ubv  = __float_as_uint(bv);
        const unsigned wmax = __reduce_max_sync(0xffffffffu, ubv);
        if (lane == 0) atomicMax(&s_bmax[buf], wmax);
        __syncthreads();                                   // bar1

        const unsigned bmax = s_bmax[buf];
        if (t == 0) {                 // reset-ahead for next iteration's buffer
            s_bmax[buf ^ 1] = 0u;
            s_gi[buf ^ 1]   = 0x7fffffff;
        }

        // lazy index resolution: only max-holding thread(s) scan
        if (ubv == bmax) {
            int c0 = 0x7fffffff, c1 = 0x7fffffff, c2 = 0x7fffffff, c3 = 0x7fffffff;
#pragma unroll
            for (int k = 7; k >= 0; k--) {                 // descending: lowest k wins
                if (md[k]      == bv) c0 = t + k * 256;
                if (md[k + 8]  == bv) c1 = t + (k + 8) * 256;
                if (md[k + 16] == bv) c2 = t + (k + 16) * 256;
                if (md[k + 24] == bv) c3 = t + (k + 24) * 256;
            }
            const int bi = min(min(c0, c1), min(c2, c3));  // lowest global idx
            atomicMin(&s_gi[buf], bi);                     // ties across threads
        }
        __syncthreads();                                   // bar2

        const int gi = s_gi[buf];
        cx = base[(size_t)gi * 3 + 0];   // same addr per warp -> L1 broadcast
        cy = base[(size_t)gi * 3 + 1];
        cz = base[(size_t)gi * 3 + 2];
        if (t == 0) {
            fpsout[i] = (float)gi;
            newxyz[(size_t)i * 3 + 0] = cx;
            newxyz[(size_t)i * 3 + 1] = cy;
            newxyz[(size_t)i * 3 + 2] = cz;
        }
    }
}

// ---------------------------------------------------------------------------
// fused ball query + grouping (R10/R14, verified, 67us): one block per center.
// 8 warps partition the N points into index-contiguous 1024-pt ranges; each
// ballot-scans its range with packed f32x2 math (2 pts/lane/round, order kept:
// lo = [p0,p0+32), hi = [p0+32,p0+64)). Ranges are index-ordered, so first-K
// overall = concat of per-warp ordered lists, merged in smem. Pad = first
// overall hit (0 if none). Then grouping: coalesced feature-row staging and
// K-contiguous channel-major writes.
// out grouped layout: (B, 3+C, S, K), channels 0..2 = recentered xyz
// ---------------------------------------------------------------------------
__global__ void __launch_bounds__(256, 4)
group_kernel(const float* __restrict__ xyz, float* __restrict__ out) {
    const int cid = blockIdx.x;
    const int b = cid / SS, s = cid % SS;
    const int tid = threadIdx.x;
    const int w = tid >> 5, lane = tid & 31;

    __shared__ int   hits[8][KK];
    __shared__ int   scnt[8];
    __shared__ int   sidx[KK];
    __shared__ float rel[3][KK];
    __shared__ float sf[KK][CC + 1];

    const float* c = out + (size_t)cid * 3;      // new_xyz lives at start of out
    const float cx = c[0], cy = c[1], cz = c[2];
    const u64 ncx = pk2(-cx, -cx), ncy = pk2(-cy, -cy), ncz = pk2(-cz, -cz);

    const float* sxp = g_sx + b * NN;
    const float* syp = g_sy + b * NN;
    const float* szp = g_sz + b * NN;

    // per-warp ordered scan of its 1024-point range
    int cnt = 0;
    const int pbeg = w * PPW;
    for (int p0 = pbeg; p0 < pbeg + PPW && cnt < KK; p0 += 64) {
        const int lo = p0 + lane, hi = p0 + 32 + lane;
        const u64 px = pk2(sxp[lo], sxp[hi]);
        const u64 py = pk2(syp[lo], syp[hi]);
        const u64 pz = pk2(szp[lo], szp[hi]);
        const u64 dx = add2(px, ncx);
        const u64 dy = add2(py, ncy);
        const u64 dz = add2(pz, ncz);
        const u64 d  = fma2(dz, dz, fma2(dy, dy, mul2(dx, dx)));
        float dl, dh; upk2(d, dl, dh);
        const bool hl = dl < R2, hh = dh < R2;
        const unsigned mlo = __ballot_sync(0xffffffffu, hl);
        const unsigned mhi = __ballot_sync(0xffffffffu, hh);
        if (mlo | mhi) {
            if (cnt == 0) {
                const int first = mlo ? (p0 + __ffs(mlo) - 1)
                                      : (p0 + 32 + __ffs(mhi) - 1);
                hits[w][lane] = first;          // pad all K slots with first hit
            }
            __syncwarp();
            const unsigned below = (1u << lane) - 1u;
            if (hl) {
                const int slot = cnt + __popc(mlo & below);
                if (slot < KK) hits[w][slot] = lo;
            }
            if (hh) {
                const int slot = cnt + __popc(mlo) + __popc(mhi & below);
                if (slot < KK) hits[w][slot] = hi;
            }
            cnt += __popc(mlo) + __popc(mhi);
        }
    }
    if (lane == 0) scnt[w] = min(cnt, KK);
    __syncthreads();

    // merge: warp 0, lane k picks the k-th hit of the 8 concatenated lists
    if (w == 0) {
        int idx = -1, acc = 0;
#pragma unroll
        for (int v = 0; v < 8; v++) {
            const int cv = scnt[v];
            if (lane >= acc && lane < acc + cv) idx = hits[v][lane - acc];
            acc += cv;
        }
        int pad = 0;
#pragma unroll
        for (int v = 7; v >= 0; v--)
            if (scnt[v] > 0) pad = hits[v][0];
        if (lane >= acc) idx = pad;             // acc = total hits (capped)
        sidx[lane] = idx;
        const float* p = xyz + ((size_t)b * NN + idx) * 3;
        rel[0][lane] = p[0] - cx;
        rel[1][lane] = p[1] - cy;
        rel[2][lane] = p[2] - cz;
    }
    __syncthreads();

    // feature staging: coalesced 256B row reads
    const int cch = tid & 63;
    const int k0  = tid >> 6;   // 0..3
    const float* ftb = g_ft + (size_t)b * NN * CC;
#pragma unroll
    for (int j = 0; j < 8; j++) {
        const int k = k0 * 8 + j;
        sf[k][cch] = ftb[(size_t)sidx[k] * CC + cch];
    }
    __syncthreads();

    float* og = out + GROUPED_OFF + (size_t)b * (CC + 3) * SS * KK + (size_t)s * KK;
    if (tid < 96) {
        const int ch = tid >> 5, k = tid & 31;
        og[(size_t)ch * (SS * KK) + k] = rel[ch][k];
    }
    const int k  = tid & 31;
    const int cg = tid >> 5;    // 0..7
#pragma unroll
    for (int j = 0; j < 8; j++) {
        const int c2 = cg * 8 + j;
        og[(size_t)(3 + c2) * (SS * KK) + k] = sf[k][c2];
    }
}

// ---------------------------------------------------------------------------
extern "C" void kernel_launch(void* const* d_in, const int* in_sizes, int n_in,
                              void* d_out, int out_size) {
    const float* xyz  = (const float*)d_in[0];
    const float* feat = (const float*)d_in[1];
    float* out = (float*)d_out;

    prep_fps_kernel<<<GRID, 256>>>(xyz, feat, out);
    group_kernel<<<BB * SS, 256>>>(xyz, out);
}